// round 12
// baseline (speedup 1.0000x reference)
#include <cuda_runtime.h>
#include <cuda_fp16.h>
#include <cstdint>

#define NMAX 50000
#define EMAX 800000
#define ETMAX (EMAX + NMAX)
#define NCHUNK ((NMAX + 255) / 256)   // 196
#define READY  (1 << 30)
#define VMASK  (READY - 1)
#define LOG2E 1.4426950408889634f

// ---------------- scratch (device globals: allocation-free) ----------------
__device__ __half g_h1h[NMAX * 128];  // layer1 pre-act features (fp16)
__device__ float g_as1[NMAX * 4];     // alpha_src * log2e
__device__ float g_ad1[NMAX * 4];     // alpha_dst * log2e
__device__ uint2 g_rec[ETMAX * 4];    // per (slot, head): {src, w_head bits}
__device__ float g_h2[NMAX * 2];
__device__ float g_as2[NMAX];         // * log2e
__device__ float g_ad2[NMAX];         // * log2e
__device__ int   g_cnt[NMAX];         // zero at entry; re-zeroed by k_scan
__device__ int   g_row[NMAX + 1];
__device__ int   g_pos[EMAX];
__device__ int   g_srcs[ETMAX];       // src per slot (for gather2)
__device__ int   g_blk[NCHUNK];       // packed (sum | READY); reset by k_scatter

__device__ __forceinline__ float lrelu(float v) { return fmaxf(v, 0.2f * v); }

// ---------------- kernel 1: feat1 (blocks < FB) || hist (rest) -------------
#define FB 400
#define HB 400
__global__ void k_feathist(const float* __restrict__ x, const int* __restrict__ ei,
                           const float* __restrict__ W1, const float* __restrict__ a_src1,
                           const float* __restrict__ a_dst1, int n, int Eo) {
    __shared__ float Ws[16 * 128];
    const int b = blockIdx.x, tid = threadIdx.x, lane = tid & 31;
    if (b < FB) {
        for (int i = tid; i < 16 * 128; i += 256) Ws[i] = W1[i];
        __syncthreads();
        int slot = tid >> 7;
        int c = tid & 127;
        int head = c >> 5;
        float as = a_src1[c], ad = a_dst1[c];
        for (int nn = b * 2 + slot; nn < n; nn += FB * 2) {
            const float4* xr = (const float4*)(x + (size_t)nn * 16);
            float4 x0 = xr[0], x1 = xr[1], x2 = xr[2], x3 = xr[3];
            float acc;
            acc  = x0.x * Ws[c];        acc += x0.y * Ws[128 + c];
            acc += x0.z * Ws[256 + c];  acc += x0.w * Ws[384 + c];
            acc += x1.x * Ws[512 + c];  acc += x1.y * Ws[640 + c];
            acc += x1.z * Ws[768 + c];  acc += x1.w * Ws[896 + c];
            acc += x2.x * Ws[1024 + c]; acc += x2.y * Ws[1152 + c];
            acc += x2.z * Ws[1280 + c]; acc += x2.w * Ws[1408 + c];
            acc += x3.x * Ws[1536 + c]; acc += x3.y * Ws[1664 + c];
            acc += x3.z * Ws[1792 + c]; acc += x3.w * Ws[1920 + c];
            g_h1h[(size_t)nn * 128 + c] = __float2half_rn(acc);
            float s = acc * as, d = acc * ad;
            #pragma unroll
            for (int o = 16; o; o >>= 1) {
                s += __shfl_down_sync(0xffffffffu, s, o);
                d += __shfl_down_sync(0xffffffffu, d, o);
            }
            if (lane == 0) {
                g_as1[nn * 4 + head] = s * LOG2E;
                g_ad1[nn * 4 + head] = d * LOG2E;
            }
        }
    } else {
        const int hb = b - FB;
        const int stride = HB * 256;
        for (int e = hb * 256 + tid; e < Eo; e += stride)
            g_pos[e] = atomicAdd(g_cnt + ei[Eo + e], 1);
    }
}

// ---------------- kernel 2: fused decoupled-lookback scan -------------------
__global__ void k_scan(int n) {
    __shared__ int sh[16];
    const int b = blockIdx.x, tid = threadIdx.x, lane = tid & 31, wp = tid >> 5;
    int i = b * 256 + tid;
    int v = (i < n) ? (g_cnt[i] + 1) : 0;
    int s = v;
    #pragma unroll
    for (int o = 1; o < 32; o <<= 1) {
        int u = __shfl_up_sync(0xffffffffu, s, o);
        if (lane >= o) s += u;
    }
    if (lane == 31) sh[8 + wp] = s;
    __syncthreads();
    if (wp == 0 && lane < 8) {
        int ws = sh[8 + lane];
        #pragma unroll
        for (int o = 1; o < 8; o <<= 1) {
            int u = __shfl_up_sync(0x000000ffu, ws, o);
            if (lane >= o) ws += u;
        }
        sh[8 + lane] = ws;
    }
    __syncthreads();
    if (tid == 0) atomicExch(g_blk + b, sh[15] | READY);
    int part = 0;
    for (int j = tid; j < b; j += 256) {
        volatile int* p = (volatile int*)(g_blk + j);
        int w;
        while (((w = *p) & READY) == 0) { }
        part += w & VMASK;
    }
    #pragma unroll
    for (int o = 16; o; o >>= 1) part += __shfl_down_sync(0xffffffffu, part, o);
    if (lane == 0) sh[wp] = part;
    __syncthreads();
    int spine = sh[0] + sh[1] + sh[2] + sh[3] + sh[4] + sh[5] + sh[6] + sh[7];
    int base = spine + (wp ? sh[8 + wp - 1] : 0);
    if (i < n) {
        int pre = base + s - v;
        g_row[i] = pre;
        g_cnt[i] = 0;
        if (i == n - 1) g_row[n] = pre + v;
    }
}

// ---------------- kernel 3: scatter srcs + packed {src,w} records -----------
__global__ void k_scatter(const int* __restrict__ ei, int Eo, int n) {
    int e = blockIdx.x * blockDim.x + threadIdx.x;
    if (e < NCHUNK) g_blk[e] = 0;     // re-arm scan flags for next replay
    int ET = Eo + n;
    if (e >= ET) return;
    int s, slot;
    float4 a, bd;
    if (e < Eo) {
        s = ei[e];
        int d = ei[Eo + e];
        slot = g_row[d] + 1 + g_pos[e];
        a  = __ldg((const float4*)g_as1 + s);
        bd = __ldg((const float4*)g_ad1 + d);
    } else {
        s = e - Eo;
        slot = g_row[s];              // self loop at bucket slot 0
        a  = __ldg((const float4*)g_as1 + s);
        bd = __ldg((const float4*)g_ad1 + s);
    }
    g_srcs[slot] = s;
    float w0 = exp2f(lrelu(a.x + bd.x));
    float w1 = exp2f(lrelu(a.y + bd.y));
    float w2 = exp2f(lrelu(a.z + bd.z));
    float w3 = exp2f(lrelu(a.w + bd.w));
    uint4* r4 = (uint4*)g_rec;
    uint4 lo, hi;
    lo.x = (unsigned)s; lo.y = __float_as_uint(w0);
    lo.z = (unsigned)s; lo.w = __float_as_uint(w1);
    hi.x = (unsigned)s; hi.y = __float_as_uint(w2);
    hi.z = (unsigned)s; hi.w = __float_as_uint(w3);
    r4[slot * 2]     = lo;
    r4[slot * 2 + 1] = hi;
}

// ---------------- kernel 4: layer1 gather (fp16 h, packed rec) --------------
// one warp per dst node; lane owns channels [lane*4, lane*4+4) as 2x half2.
__device__ __forceinline__ void acc_edge(uint2 u, float w,
                                         float& ax, float& ay, float& az, float& aw) {
    float2 fa = __half22float2(*reinterpret_cast<__half2*>(&u.x));
    float2 fb = __half22float2(*reinterpret_cast<__half2*>(&u.y));
    ax = fmaf(w, fa.x, ax); ay = fmaf(w, fa.y, ay);
    az = fmaf(w, fb.x, az); aw = fmaf(w, fb.y, aw);
}

__global__ void k_gather1(const float* __restrict__ b1, const float* __restrict__ W2,
                          const float* __restrict__ a_src2, const float* __restrict__ a_dst2,
                          int n_nodes) {
    int t = blockIdx.x * blockDim.x + threadIdx.x;
    int d = t >> 5, lane = t & 31;
    if (d >= n_nodes) return;
    int head = lane >> 3;
    int c0 = lane * 4;

    float ax = 0.f, ay = 0.f, az = 0.f, aw = 0.f, den = 0.f;

    int p = g_row[d], pend = g_row[d + 1];
    const uint2* rec = g_rec + head;   // index by 4*slot
    for (; p + 4 <= pend; p += 4) {
        uint2 r0 = __ldg(rec + (p + 0) * 4);
        uint2 r1 = __ldg(rec + (p + 1) * 4);
        uint2 r2 = __ldg(rec + (p + 2) * 4);
        uint2 r3 = __ldg(rec + (p + 3) * 4);
        float w0 = __uint_as_float(r0.y);
        float w1 = __uint_as_float(r1.y);
        float w2 = __uint_as_float(r2.y);
        float w3 = __uint_as_float(r3.y);
        uint2 u0 = *(const uint2*)(g_h1h + (size_t)r0.x * 128 + c0);
        uint2 u1 = *(const uint2*)(g_h1h + (size_t)r1.x * 128 + c0);
        uint2 u2 = *(const uint2*)(g_h1h + (size_t)r2.x * 128 + c0);
        uint2 u3 = *(const uint2*)(g_h1h + (size_t)r3.x * 128 + c0);
        den += (w0 + w1) + (w2 + w3);
        acc_edge(u0, w0, ax, ay, az, aw);
        acc_edge(u1, w1, ax, ay, az, aw);
        acc_edge(u2, w2, ax, ay, az, aw);
        acc_edge(u3, w3, ax, ay, az, aw);
    }
    for (; p < pend; ++p) {
        uint2 r = __ldg(rec + p * 4);
        float w = __uint_as_float(r.y);
        den += w;
        uint2 u = *(const uint2*)(g_h1h + (size_t)r.x * 128 + c0);
        acc_edge(u, w, ax, ay, az, aw);
    }
    float inv = 1.f / (den + 1e-16f);
    float4 bb = *(const float4*)(b1 + c0);
    float v0 = fmaxf(ax * inv + bb.x, 0.f);
    float v1 = fmaxf(ay * inv + bb.y, 0.f);
    float v2 = fmaxf(az * inv + bb.z, 0.f);
    float v3 = fmaxf(aw * inv + bb.w, 0.f);
    float4 wA = *(const float4*)(W2 + c0 * 2);
    float4 wB = *(const float4*)(W2 + c0 * 2 + 4);
    float pq0 = v0 * wA.x + v1 * wA.z + v2 * wB.x + v3 * wB.z;
    float pq1 = v0 * wA.y + v1 * wA.w + v2 * wB.y + v3 * wB.w;
    #pragma unroll
    for (int o = 16; o; o >>= 1) {
        pq0 += __shfl_down_sync(0xffffffffu, pq0, o);
        pq1 += __shfl_down_sync(0xffffffffu, pq1, o);
    }
    if (lane == 0) {
        g_h2[d * 2] = pq0; g_h2[d * 2 + 1] = pq1;
        g_as2[d] = (pq0 * a_src2[0] + pq1 * a_src2[1]) * LOG2E;
        g_ad2[d] = (pq0 * a_dst2[0] + pq1 * a_dst2[1]) * LOG2E;
    }
}

// ---------------- kernel 5: layer2 gather -> output -------------------------
__global__ void k_gather2(float* __restrict__ out, const float* __restrict__ b2,
                          int n_nodes) {
    int t = blockIdx.x * blockDim.x + threadIdx.x;
    int d = t >> 5, lane = t & 31;
    if (d >= n_nodes) return;
    float add = g_ad2[d];
    float wsum = 0.f, s0 = 0.f, s1 = 0.f;
    int p0 = g_row[d], pend = g_row[d + 1];
    for (int p = p0 + lane; p < pend; p += 32) {
        int s = __ldg(g_srcs + p);
        float w = exp2f(lrelu(__ldg(g_as2 + s) + add));
        wsum += w;
        float2 h = *(const float2*)(g_h2 + s * 2);
        s0 = fmaf(w, h.x, s0);
        s1 = fmaf(w, h.y, s1);
    }
    #pragma unroll
    for (int o = 16; o; o >>= 1) {
        wsum += __shfl_down_sync(0xffffffffu, wsum, o);
        s0   += __shfl_down_sync(0xffffffffu, s0, o);
        s1   += __shfl_down_sync(0xffffffffu, s1, o);
    }
    if (lane == 0) {
        float inv = 1.f / (wsum + 1e-16f);
        out[d * 2]     = s0 * inv + b2[0];
        out[d * 2 + 1] = s1 * inv + b2[1];
    }
}

extern "C" void kernel_launch(void* const* d_in, const int* in_sizes, int n_in,
                              void* d_out, int out_size) {
    const float* x   = (const float*)d_in[0];
    const int*   ei  = (const int*)d_in[1];
    const float* W1  = (const float*)d_in[2];
    const float* as1 = (const float*)d_in[3];
    const float* ad1 = (const float*)d_in[4];
    const float* b1  = (const float*)d_in[5];
    const float* W2  = (const float*)d_in[6];
    const float* as2 = (const float*)d_in[7];
    const float* ad2 = (const float*)d_in[8];
    const float* b2  = (const float*)d_in[9];
    float* out = (float*)d_out;

    int n  = in_sizes[0] / 16;   // nodes
    int Eo = in_sizes[1] / 2;    // original edges
    int ET = Eo + n;

    k_feathist<<<FB + HB, 256>>>(x, ei, W1, as1, ad1, n, Eo);
    k_scan<<<NCHUNK, 256>>>(n);
    k_scatter<<<(ET + 255) / 256, 256>>>(ei, Eo, n);
    int warps_grid = (n * 32 + 255) / 256;
    k_gather1<<<warps_grid, 256>>>(b1, W2, as2, ad2, n);
    k_gather2<<<warps_grid, 256>>>(out, b2, n);
}

// round 13
// speedup vs baseline: 1.0786x; 1.0786x over previous
#include <cuda_runtime.h>
#include <cstdint>

#define NMAX 50000
#define EMAX 800000
#define ETMAX (EMAX + NMAX)
#define NCHUNK ((NMAX + 255) / 256)   // 196
#define READY  (1 << 30)
#define VMASK  (READY - 1)
#define LOG2E 1.4426950408889634f
#define SCT_BLKS 840                  // >= NCHUNK and >= ceil(ET/1024); all resident

// ---------------- scratch (device globals: allocation-free) ----------------
__device__ float g_h1[NMAX * 128];    // layer1 pre-act features
__device__ float g_as1[NMAX * 4];     // alpha_src * log2e
__device__ float g_ad1[NMAX * 4];     // alpha_dst * log2e
__device__ float4 g_n2[NMAX];         // {h2x, h2y, as2*log2e, ad2*log2e}
__device__ int   g_cnt[NMAX];         // zero at entry; re-zeroed by scan phase
__device__ int   g_row[NMAX + 1];
__device__ int   g_pos[EMAX];
__device__ int   g_srcs[ETMAX];
__device__ int   g_blk[NCHUNK];       // packed (sum | READY); reset post-barrier
__device__ unsigned g_done1, g_done2; // intra-kernel barrier gen counters (self-reset)

__device__ __forceinline__ float lrelu(float v) { return fmaxf(v, 0.2f * v); }

// ---------------- kernel 1: feat1 (blocks < FB) || hist (rest) -------------
#define FB 400
#define HB 400
__global__ void k_feathist(const float* __restrict__ x, const int* __restrict__ ei,
                           const float* __restrict__ W1, const float* __restrict__ a_src1,
                           const float* __restrict__ a_dst1, int n, int Eo) {
    __shared__ float Ws[16 * 128];
    const int b = blockIdx.x, tid = threadIdx.x, lane = tid & 31;
    if (b < FB) {
        for (int i = tid; i < 16 * 128; i += 256) Ws[i] = W1[i];
        __syncthreads();
        int slot = tid >> 7;
        int c = tid & 127;
        int head = c >> 5;
        float as = a_src1[c], ad = a_dst1[c];
        for (int nn = b * 2 + slot; nn < n; nn += FB * 2) {
            const float4* xr = (const float4*)(x + (size_t)nn * 16);
            float4 x0 = xr[0], x1 = xr[1], x2 = xr[2], x3 = xr[3];
            float acc;
            acc  = x0.x * Ws[c];        acc += x0.y * Ws[128 + c];
            acc += x0.z * Ws[256 + c];  acc += x0.w * Ws[384 + c];
            acc += x1.x * Ws[512 + c];  acc += x1.y * Ws[640 + c];
            acc += x1.z * Ws[768 + c];  acc += x1.w * Ws[896 + c];
            acc += x2.x * Ws[1024 + c]; acc += x2.y * Ws[1152 + c];
            acc += x2.z * Ws[1280 + c]; acc += x2.w * Ws[1408 + c];
            acc += x3.x * Ws[1536 + c]; acc += x3.y * Ws[1664 + c];
            acc += x3.z * Ws[1792 + c]; acc += x3.w * Ws[1920 + c];
            g_h1[(size_t)nn * 128 + c] = acc;
            float s = acc * as, d = acc * ad;
            #pragma unroll
            for (int o = 16; o; o >>= 1) {
                s += __shfl_down_sync(0xffffffffu, s, o);
                d += __shfl_down_sync(0xffffffffu, d, o);
            }
            if (lane == 0) {
                g_as1[nn * 4 + head] = s * LOG2E;
                g_ad1[nn * 4 + head] = d * LOG2E;
            }
        }
    } else {
        const int hb = b - FB;
        const int stride = HB * 256;
        for (int e = hb * 256 + tid; e < Eo; e += stride)
            g_pos[e] = atomicAdd(g_cnt + ei[Eo + e], 1);
    }
}

// ---------------- kernel 2: fused scan (lookback) + scatter -----------------
// Blocks [0, NCHUNK) do the scan; ALL blocks then spin on a completion counter
// and perform the scatter. All SCT_BLKS blocks are co-resident => no deadlock.
__global__ void __launch_bounds__(256, 8) k_scansct(const int* __restrict__ ei,
                                                    int Eo, int n) {
    __shared__ int sh[16];
    const int b = blockIdx.x, tid = threadIdx.x, lane = tid & 31, wp = tid >> 5;

    if (b < NCHUNK) {
        int i = b * 256 + tid;
        int v = (i < n) ? (g_cnt[i] + 1) : 0;
        int s = v;
        #pragma unroll
        for (int o = 1; o < 32; o <<= 1) {
            int u = __shfl_up_sync(0xffffffffu, s, o);
            if (lane >= o) s += u;
        }
        if (lane == 31) sh[8 + wp] = s;
        __syncthreads();
        if (wp == 0 && lane < 8) {
            int ws = sh[8 + lane];
            #pragma unroll
            for (int o = 1; o < 8; o <<= 1) {
                int u = __shfl_up_sync(0x000000ffu, ws, o);
                if (lane >= o) ws += u;
            }
            sh[8 + lane] = ws;
        }
        __syncthreads();
        if (tid == 0) atomicExch(g_blk + b, sh[15] | READY);
        int part = 0;
        for (int j = tid; j < b; j += 256) {
            volatile int* p = (volatile int*)(g_blk + j);
            int w;
            while (((w = *p) & READY) == 0) { }
            part += w & VMASK;
        }
        #pragma unroll
        for (int o = 16; o; o >>= 1) part += __shfl_down_sync(0xffffffffu, part, o);
        if (lane == 0) sh[wp] = part;
        __syncthreads();
        int spine = sh[0] + sh[1] + sh[2] + sh[3] + sh[4] + sh[5] + sh[6] + sh[7];
        int base = spine + (wp ? sh[8 + wp - 1] : 0);
        if (i < n) {
            int pre = base + s - v;
            g_row[i] = pre;
            g_cnt[i] = 0;
            if (i == n - 1) g_row[n] = pre + v;
        }
        __syncthreads();
        if (tid == 0) { __threadfence(); atomicAdd(&g_done1, 1u); }
    }

    // wait until all scan chunks (incl. g_row writes) are globally visible
    if (tid == 0) {
        while (((volatile unsigned*)&g_done1)[0] < (unsigned)NCHUNK) __nanosleep(32);
        __threadfence();
    }
    __syncthreads();

    // reset scan flags for the next graph replay (safe: all lookbacks done)
    if (b < NCHUNK && tid == 0) g_blk[b] = 0;

    // scatter: 4 edges per thread, atomic-free
    int base4 = (b * 256 + tid) * 4;
    #pragma unroll
    for (int k = 0; k < 4; k++) {
        int e = base4 + k;
        if (e < Eo) {
            int s = ei[e], d = ei[Eo + e];
            g_srcs[g_row[d] + 1 + g_pos[e]] = s;
        } else {
            int i = e - Eo;
            if (i < n) g_srcs[g_row[i]] = i;   // self loop at slot 0
        }
    }

    // generation reset: last block to finish clears both counters
    __syncthreads();
    if (tid == 0) {
        unsigned r = atomicAdd(&g_done2, 1u);
        if (r == (unsigned)SCT_BLKS - 1u) { g_done2 = 0u; g_done1 = 0u; __threadfence(); }
    }
}

// ---------------- kernel 3: layer1 gather + epilogue -> packed node rec -----
// one warp per dst node; lane owns channels [lane*4, lane*4+4).
__global__ void k_gather1(const float* __restrict__ b1, const float* __restrict__ W2,
                          const float* __restrict__ a_src2, const float* __restrict__ a_dst2,
                          int n_nodes) {
    int t = blockIdx.x * blockDim.x + threadIdx.x;
    int d = t >> 5, lane = t & 31;
    if (d >= n_nodes) return;
    int head = lane >> 3;
    int c0 = lane * 4;

    float adh = __ldg(g_ad1 + d * 4 + head);
    float ax = 0.f, ay = 0.f, az = 0.f, aw = 0.f, den = 0.f;

    int p = g_row[d], pend = g_row[d + 1];
    for (; p + 4 <= pend; p += 4) {
        int s0 = __ldg(g_srcs + p);
        int s1 = __ldg(g_srcs + p + 1);
        int s2 = __ldg(g_srcs + p + 2);
        int s3 = __ldg(g_srcs + p + 3);
        float l0 = __ldg(g_as1 + s0 * 4 + head);
        float l1 = __ldg(g_as1 + s1 * 4 + head);
        float l2 = __ldg(g_as1 + s2 * 4 + head);
        float l3 = __ldg(g_as1 + s3 * 4 + head);
        float4 h0 = *(const float4*)(g_h1 + (size_t)s0 * 128 + c0);
        float4 h1 = *(const float4*)(g_h1 + (size_t)s1 * 128 + c0);
        float4 h2 = *(const float4*)(g_h1 + (size_t)s2 * 128 + c0);
        float4 h3 = *(const float4*)(g_h1 + (size_t)s3 * 128 + c0);
        float w0 = exp2f(lrelu(l0 + adh));
        float w1 = exp2f(lrelu(l1 + adh));
        float w2 = exp2f(lrelu(l2 + adh));
        float w3 = exp2f(lrelu(l3 + adh));
        den += (w0 + w1) + (w2 + w3);
        ax = fmaf(w0, h0.x, ax); ay = fmaf(w0, h0.y, ay);
        az = fmaf(w0, h0.z, az); aw = fmaf(w0, h0.w, aw);
        ax = fmaf(w1, h1.x, ax); ay = fmaf(w1, h1.y, ay);
        az = fmaf(w1, h1.z, az); aw = fmaf(w1, h1.w, aw);
        ax = fmaf(w2, h2.x, ax); ay = fmaf(w2, h2.y, ay);
        az = fmaf(w2, h2.z, az); aw = fmaf(w2, h2.w, aw);
        ax = fmaf(w3, h3.x, ax); ay = fmaf(w3, h3.y, ay);
        az = fmaf(w3, h3.z, az); aw = fmaf(w3, h3.w, aw);
    }
    for (; p < pend; ++p) {
        int s = __ldg(g_srcs + p);
        float w = exp2f(lrelu(__ldg(g_as1 + s * 4 + head) + adh));
        den += w;
        float4 h = *(const float4*)(g_h1 + (size_t)s * 128 + c0);
        ax = fmaf(w, h.x, ax); ay = fmaf(w, h.y, ay);
        az = fmaf(w, h.z, az); aw = fmaf(w, h.w, aw);
    }
    float inv = 1.f / (den + 1e-16f);
    float4 bb = *(const float4*)(b1 + c0);
    float v0 = fmaxf(ax * inv + bb.x, 0.f);
    float v1 = fmaxf(ay * inv + bb.y, 0.f);
    float v2 = fmaxf(az * inv + bb.z, 0.f);
    float v3 = fmaxf(aw * inv + bb.w, 0.f);
    float4 wA = *(const float4*)(W2 + c0 * 2);
    float4 wB = *(const float4*)(W2 + c0 * 2 + 4);
    float pq0 = v0 * wA.x + v1 * wA.z + v2 * wB.x + v3 * wB.z;
    float pq1 = v0 * wA.y + v1 * wA.w + v2 * wB.y + v3 * wB.w;
    #pragma unroll
    for (int o = 16; o; o >>= 1) {
        pq0 += __shfl_down_sync(0xffffffffu, pq0, o);
        pq1 += __shfl_down_sync(0xffffffffu, pq1, o);
    }
    if (lane == 0) {
        float4 r;
        r.x = pq0; r.y = pq1;
        r.z = (pq0 * a_src2[0] + pq1 * a_src2[1]) * LOG2E;
        r.w = (pq0 * a_dst2[0] + pq1 * a_dst2[1]) * LOG2E;
        g_n2[d] = r;
    }
}

// ---------------- kernel 4: layer2 gather (1 LDG.128/edge) -> output --------
__global__ void k_gather2(float* __restrict__ out, const float* __restrict__ b2,
                          int n_nodes) {
    int t = blockIdx.x * blockDim.x + threadIdx.x;
    int d = t >> 5, lane = t & 31;
    if (d >= n_nodes) return;
    float add = __ldg(&g_n2[d].w);
    float wsum = 0.f, s0 = 0.f, s1 = 0.f;
    int p0 = g_row[d], pend = g_row[d + 1];
    for (int p = p0 + lane; p < pend; p += 32) {
        int s = __ldg(g_srcs + p);
        float4 r = __ldg(g_n2 + s);
        float w = exp2f(lrelu(r.z + add));
        wsum += w;
        s0 = fmaf(w, r.x, s0);
        s1 = fmaf(w, r.y, s1);
    }
    #pragma unroll
    for (int o = 16; o; o >>= 1) {
        wsum += __shfl_down_sync(0xffffffffu, wsum, o);
        s0   += __shfl_down_sync(0xffffffffu, s0, o);
        s1   += __shfl_down_sync(0xffffffffu, s1, o);
    }
    if (lane == 0) {
        float inv = 1.f / (wsum + 1e-16f);
        out[d * 2]     = s0 * inv + b2[0];
        out[d * 2 + 1] = s1 * inv + b2[1];
    }
}

extern "C" void kernel_launch(void* const* d_in, const int* in_sizes, int n_in,
                              void* d_out, int out_size) {
    const float* x   = (const float*)d_in[0];
    const int*   ei  = (const int*)d_in[1];
    const float* W1  = (const float*)d_in[2];
    const float* as1 = (const float*)d_in[3];
    const float* ad1 = (const float*)d_in[4];
    const float* b1  = (const float*)d_in[5];
    const float* W2  = (const float*)d_in[6];
    const float* as2 = (const float*)d_in[7];
    const float* ad2 = (const float*)d_in[8];
    const float* b2  = (const float*)d_in[9];
    float* out = (float*)d_out;

    int n  = in_sizes[0] / 16;   // nodes
    int Eo = in_sizes[1] / 2;    // original edges

    k_feathist<<<FB + HB, 256>>>(x, ei, W1, as1, ad1, n, Eo);
    k_scansct<<<SCT_BLKS, 256>>>(ei, Eo, n);
    int warps_grid = (n * 32 + 255) / 256;
    k_gather1<<<warps_grid, 256>>>(b1, W2, as2, ad2, n);
    k_gather2<<<warps_grid, 256>>>(out, b2, n);
}

// round 14
// speedup vs baseline: 1.1303x; 1.0480x over previous
#include <cuda_runtime.h>
#include <cstdint>

#define NMAX 50000
#define EMAX 800000
#define ETMAX (EMAX + NMAX)
#define NCHUNK ((NMAX + 255) / 256)   // 196
#define READY  (1 << 30)
#define VMASK  (READY - 1)
#define LOG2E 1.4426950408889634f
#define SCT_BLKS 840                  // >= NCHUNK and >= ceil(ET/1024); all resident

// ---------------- scratch (device globals: allocation-free) ----------------
__device__ float g_h1[NMAX * 128];    // layer1 pre-act features
__device__ float g_as1[NMAX * 4];     // alpha_src * log2e
__device__ float g_ad1[NMAX * 4];     // alpha_dst * log2e
__device__ float4 g_n2[NMAX];         // {h2x, h2y, as2*log2e, ad2*log2e}
__device__ int   g_cnt[NMAX];         // zero at entry; re-zeroed by scan phase
__device__ int   g_row[NMAX + 1];
__device__ int   g_pos[EMAX];
__device__ int   g_srcs[ETMAX];
__device__ int   g_blk[NCHUNK];       // packed (sum | READY); reset post-barrier
__device__ unsigned g_done1, g_done2; // intra-kernel barrier gen counters (self-reset)

__device__ __forceinline__ float lrelu(float v) { return fmaxf(v, 0.2f * v); }

// ---------------- kernel 1: feat1 (blocks < FB) || hist (rest) -------------
#define FB 400
#define HB 400
__global__ void k_feathist(const float* __restrict__ x, const int* __restrict__ ei,
                           const float* __restrict__ W1, const float* __restrict__ a_src1,
                           const float* __restrict__ a_dst1, int n, int Eo) {
    __shared__ float Ws[16 * 128];
    const int b = blockIdx.x, tid = threadIdx.x, lane = tid & 31;
    if (b < FB) {
        for (int i = tid; i < 16 * 128; i += 256) Ws[i] = W1[i];
        __syncthreads();
        int slot = tid >> 7;
        int c = tid & 127;
        int head = c >> 5;
        float as = a_src1[c], ad = a_dst1[c];
        for (int nn = b * 2 + slot; nn < n; nn += FB * 2) {
            const float4* xr = (const float4*)(x + (size_t)nn * 16);
            float4 x0 = xr[0], x1 = xr[1], x2 = xr[2], x3 = xr[3];
            float acc;
            acc  = x0.x * Ws[c];        acc += x0.y * Ws[128 + c];
            acc += x0.z * Ws[256 + c];  acc += x0.w * Ws[384 + c];
            acc += x1.x * Ws[512 + c];  acc += x1.y * Ws[640 + c];
            acc += x1.z * Ws[768 + c];  acc += x1.w * Ws[896 + c];
            acc += x2.x * Ws[1024 + c]; acc += x2.y * Ws[1152 + c];
            acc += x2.z * Ws[1280 + c]; acc += x2.w * Ws[1408 + c];
            acc += x3.x * Ws[1536 + c]; acc += x3.y * Ws[1664 + c];
            acc += x3.z * Ws[1792 + c]; acc += x3.w * Ws[1920 + c];
            g_h1[(size_t)nn * 128 + c] = acc;
            float s = acc * as, d = acc * ad;
            #pragma unroll
            for (int o = 16; o; o >>= 1) {
                s += __shfl_down_sync(0xffffffffu, s, o);
                d += __shfl_down_sync(0xffffffffu, d, o);
            }
            if (lane == 0) {
                g_as1[nn * 4 + head] = s * LOG2E;
                g_ad1[nn * 4 + head] = d * LOG2E;
            }
        }
    } else {
        const int hb = b - FB;
        const int stride = HB * 256;
        for (int e = hb * 256 + tid; e < Eo; e += stride)
            g_pos[e] = atomicAdd(g_cnt + ei[Eo + e], 1);
    }
}

// ---------------- kernel 2: fused scan (lookback) + scatter -----------------
__global__ void __launch_bounds__(256, 8) k_scansct(const int* __restrict__ ei,
                                                    int Eo, int n) {
    __shared__ int sh[16];
    const int b = blockIdx.x, tid = threadIdx.x, lane = tid & 31, wp = tid >> 5;

    if (b < NCHUNK) {
        int i = b * 256 + tid;
        int v = (i < n) ? (g_cnt[i] + 1) : 0;
        int s = v;
        #pragma unroll
        for (int o = 1; o < 32; o <<= 1) {
            int u = __shfl_up_sync(0xffffffffu, s, o);
            if (lane >= o) s += u;
        }
        if (lane == 31) sh[8 + wp] = s;
        __syncthreads();
        if (wp == 0 && lane < 8) {
            int ws = sh[8 + lane];
            #pragma unroll
            for (int o = 1; o < 8; o <<= 1) {
                int u = __shfl_up_sync(0x000000ffu, ws, o);
                if (lane >= o) ws += u;
            }
            sh[8 + lane] = ws;
        }
        __syncthreads();
        if (tid == 0) atomicExch(g_blk + b, sh[15] | READY);
        int part = 0;
        for (int j = tid; j < b; j += 256) {
            volatile int* p = (volatile int*)(g_blk + j);
            int w;
            while (((w = *p) & READY) == 0) { }
            part += w & VMASK;
        }
        #pragma unroll
        for (int o = 16; o; o >>= 1) part += __shfl_down_sync(0xffffffffu, part, o);
        if (lane == 0) sh[wp] = part;
        __syncthreads();
        int spine = sh[0] + sh[1] + sh[2] + sh[3] + sh[4] + sh[5] + sh[6] + sh[7];
        int base = spine + (wp ? sh[8 + wp - 1] : 0);
        if (i < n) {
            int pre = base + s - v;
            g_row[i] = pre;
            g_cnt[i] = 0;
            if (i == n - 1) g_row[n] = pre + v;
        }
        __syncthreads();
        if (tid == 0) { __threadfence(); atomicAdd(&g_done1, 1u); }
    }

    if (tid == 0) {
        while (((volatile unsigned*)&g_done1)[0] < (unsigned)NCHUNK) __nanosleep(32);
        __threadfence();
    }
    __syncthreads();

    if (b < NCHUNK && tid == 0) g_blk[b] = 0;

    int base4 = (b * 256 + tid) * 4;
    #pragma unroll
    for (int k = 0; k < 4; k++) {
        int e = base4 + k;
        if (e < Eo) {
            int s = ei[e], d = ei[Eo + e];
            g_srcs[g_row[d] + 1 + g_pos[e]] = s;
        } else {
            int i = e - Eo;
            if (i < n) g_srcs[g_row[i]] = i;   // self loop at slot 0
        }
    }

    __syncthreads();
    if (tid == 0) {
        unsigned r = atomicAdd(&g_done2, 1u);
        if (r == (unsigned)SCT_BLKS - 1u) { g_done2 = 0u; g_done1 = 0u; __threadfence(); }
    }
}

// ---------------- kernel 3: layer1 gather + epilogue -> packed node rec -----
__global__ void k_gather1(const float* __restrict__ b1, const float* __restrict__ W2,
                          const float* __restrict__ a_src2, const float* __restrict__ a_dst2,
                          int n_nodes) {
    int t = blockIdx.x * blockDim.x + threadIdx.x;
    int d = t >> 5, lane = t & 31;
    if (d >= n_nodes) return;
    int head = lane >> 3;
    int c0 = lane * 4;

    float adh = __ldg(g_ad1 + d * 4 + head);
    float ax = 0.f, ay = 0.f, az = 0.f, aw = 0.f, den = 0.f;

    int p = g_row[d], pend = g_row[d + 1];
    for (; p + 4 <= pend; p += 4) {
        int s0 = __ldg(g_srcs + p);
        int s1 = __ldg(g_srcs + p + 1);
        int s2 = __ldg(g_srcs + p + 2);
        int s3 = __ldg(g_srcs + p + 3);
        float l0 = __ldg(g_as1 + s0 * 4 + head);
        float l1 = __ldg(g_as1 + s1 * 4 + head);
        float l2 = __ldg(g_as1 + s2 * 4 + head);
        float l3 = __ldg(g_as1 + s3 * 4 + head);
        float4 h0 = *(const float4*)(g_h1 + (size_t)s0 * 128 + c0);
        float4 h1 = *(const float4*)(g_h1 + (size_t)s1 * 128 + c0);
        float4 h2 = *(const float4*)(g_h1 + (size_t)s2 * 128 + c0);
        float4 h3 = *(const float4*)(g_h1 + (size_t)s3 * 128 + c0);
        float w0 = exp2f(lrelu(l0 + adh));
        float w1 = exp2f(lrelu(l1 + adh));
        float w2 = exp2f(lrelu(l2 + adh));
        float w3 = exp2f(lrelu(l3 + adh));
        den += (w0 + w1) + (w2 + w3);
        ax = fmaf(w0, h0.x, ax); ay = fmaf(w0, h0.y, ay);
        az = fmaf(w0, h0.z, az); aw = fmaf(w0, h0.w, aw);
        ax = fmaf(w1, h1.x, ax); ay = fmaf(w1, h1.y, ay);
        az = fmaf(w1, h1.z, az); aw = fmaf(w1, h1.w, aw);
        ax = fmaf(w2, h2.x, ax); ay = fmaf(w2, h2.y, ay);
        az = fmaf(w2, h2.z, az); aw = fmaf(w2, h2.w, aw);
        ax = fmaf(w3, h3.x, ax); ay = fmaf(w3, h3.y, ay);
        az = fmaf(w3, h3.z, az); aw = fmaf(w3, h3.w, aw);
    }
    for (; p < pend; ++p) {
        int s = __ldg(g_srcs + p);
        float w = exp2f(lrelu(__ldg(g_as1 + s * 4 + head) + adh));
        den += w;
        float4 h = *(const float4*)(g_h1 + (size_t)s * 128 + c0);
        ax = fmaf(w, h.x, ax); ay = fmaf(w, h.y, ay);
        az = fmaf(w, h.z, az); aw = fmaf(w, h.w, aw);
    }
    float inv = 1.f / (den + 1e-16f);
    float4 bb = *(const float4*)(b1 + c0);
    float v0 = fmaxf(ax * inv + bb.x, 0.f);
    float v1 = fmaxf(ay * inv + bb.y, 0.f);
    float v2 = fmaxf(az * inv + bb.z, 0.f);
    float v3 = fmaxf(aw * inv + bb.w, 0.f);
    float4 wA = *(const float4*)(W2 + c0 * 2);
    float4 wB = *(const float4*)(W2 + c0 * 2 + 4);
    float pq0 = v0 * wA.x + v1 * wA.z + v2 * wB.x + v3 * wB.z;
    float pq1 = v0 * wA.y + v1 * wA.w + v2 * wB.y + v3 * wB.w;
    #pragma unroll
    for (int o = 16; o; o >>= 1) {
        pq0 += __shfl_down_sync(0xffffffffu, pq0, o);
        pq1 += __shfl_down_sync(0xffffffffu, pq1, o);
    }
    if (lane == 0) {
        float4 r;
        r.x = pq0; r.y = pq1;
        r.z = (pq0 * a_src2[0] + pq1 * a_src2[1]) * LOG2E;
        r.w = (pq0 * a_dst2[0] + pq1 * a_dst2[1]) * LOG2E;
        g_n2[d] = r;
    }
}

// ---------------- kernel 4: layer2 gather, 8 lanes/dst, 4 dsts/warp ---------
__global__ void k_gather2(float* __restrict__ out, const float* __restrict__ b2,
                          int n_nodes) {
    int t = blockIdx.x * blockDim.x + threadIdx.x;
    int warp = t >> 5, lane = t & 31;
    int sub = lane >> 3;          // 0..3: which dst within the warp
    int sl = lane & 7;            // lane within subgroup
    int d = warp * 4 + sub;
    if (d >= n_nodes) return;
    float add = __ldg(&((const float*)g_n2)[d * 4 + 3]);
    float wsum = 0.f, s0 = 0.f, s1 = 0.f;
    int p0 = g_row[d], pend = g_row[d + 1];
    for (int p = p0 + sl; p < pend; p += 8) {
        int s = __ldg(g_srcs + p);
        float4 r = __ldg(g_n2 + s);
        float w = exp2f(lrelu(r.z + add));
        wsum += w;
        s0 = fmaf(w, r.x, s0);
        s1 = fmaf(w, r.y, s1);
    }
    #pragma unroll
    for (int o = 4; o; o >>= 1) {
        wsum += __shfl_xor_sync(0xffffffffu, wsum, o);
        s0   += __shfl_xor_sync(0xffffffffu, s0, o);
        s1   += __shfl_xor_sync(0xffffffffu, s1, o);
    }
    if (sl == 0) {
        float inv = 1.f / (wsum + 1e-16f);
        out[d * 2]     = s0 * inv + b2[0];
        out[d * 2 + 1] = s1 * inv + b2[1];
    }
}

extern "C" void kernel_launch(void* const* d_in, const int* in_sizes, int n_in,
                              void* d_out, int out_size) {
    const float* x   = (const float*)d_in[0];
    const int*   ei  = (const int*)d_in[1];
    const float* W1  = (const float*)d_in[2];
    const float* as1 = (const float*)d_in[3];
    const float* ad1 = (const float*)d_in[4];
    const float* b1  = (const float*)d_in[5];
    const float* W2  = (const float*)d_in[6];
    const float* as2 = (const float*)d_in[7];
    const float* ad2 = (const float*)d_in[8];
    const float* b2  = (const float*)d_in[9];
    float* out = (float*)d_out;

    int n  = in_sizes[0] / 16;   // nodes
    int Eo = in_sizes[1] / 2;    // original edges

    k_feathist<<<FB + HB, 256>>>(x, ei, W1, as1, ad1, n, Eo);
    k_scansct<<<SCT_BLKS, 256>>>(ei, Eo, n);
    int warps_grid = (n * 32 + 255) / 256;
    k_gather1<<<warps_grid, 256>>>(b1, W2, as2, ad2, n);
    int g2_grid = (n * 8 + 255) / 256;   // 8 threads per dst
    k_gather2<<<g2_grid, 256>>>(out, b2, n);
}